// round 11
// baseline (speedup 1.0000x reference)
#include <cuda_runtime.h>
#include <cstdint>

#define FD 1024
#define RD 64
#define MT 128
#define NCH 16          // GEMM1 chunks of 64 cols

// ---------------- device scratch ----------------
__device__ float g_Gp[8][RD * RD];      // partial Gram matrices
__device__ float g_Minv[RD * RD];
__device__ uint4 g_PP[64 * 8 * 32];     // GEMM1 B frags
__device__ uint4 g_WP[128 * 4 * 32];    // GEMM2 B frags
__device__ uint4 g_MP[8 * 4 * 32];      // d3 B frags (Minv)
__device__ int   g_flag_inv;
__device__ int   g_flag_wp;

// ---------------- helpers ----------------
__device__ __forceinline__ void split2(float x, float y, uint32_t& hi, uint32_t& lo) {
    asm("cvt.rn.bf16x2.f32 %0, %1, %2;" : "=r"(hi) : "f"(y), "f"(x));
    float xr = x - __uint_as_float(hi << 16);
    float yr = y - __uint_as_float(hi & 0xffff0000u);
    asm("cvt.rn.bf16x2.f32 %0, %1, %2;" : "=r"(lo) : "f"(yr), "f"(xr));
}

__device__ __forceinline__ void mma_bf16(float* d,
    uint32_t a0, uint32_t a1, uint32_t a2, uint32_t a3,
    uint32_t b0, uint32_t b1) {
    asm volatile("mma.sync.aligned.m16n8k16.row.col.f32.bf16.bf16.f32 "
        "{%0,%1,%2,%3}, {%4,%5,%6,%7}, {%8,%9}, {%0,%1,%2,%3};"
        : "+f"(d[0]), "+f"(d[1]), "+f"(d[2]), "+f"(d[3])
        : "r"(a0), "r"(a1), "r"(a2), "r"(a3), "r"(b0), "r"(b1));
}

__device__ __forceinline__ void cpa16(uint32_t s, const void* g) {
    asm volatile("cp.async.cg.shared.global [%0], [%1], 16;" :: "r"(s), "l"(g));
}
#define CP_COMMIT asm volatile("cp.async.commit_group;" ::: "memory")
#define CP_WAIT0  asm volatile("cp.async.wait_group 0;" ::: "memory")

// ---------------- prep: partial gram (blocks 0-7) + pack P (all 64) + flag reset ----------------
__global__ void k_prep1(const float* __restrict__ probe) {
    __shared__ float Ps[128][68];
    int t = threadIdx.x;
    if (blockIdx.x == 0 && t == 0) { g_flag_inv = 0; g_flag_wp = 0; }
    if (blockIdx.x < 8) {
        int c = blockIdx.x;
        #pragma unroll
        for (int i = 0; i < 8; i++) {
            int idx = t + 256 * i;
            int fl = idx >> 4, r4 = (idx & 15) << 2;
            float4 v = *(const float4*)(probe + (c * 128 + fl) * 64 + r4);
            *(float4*)(&Ps[fl][r4]) = v;
        }
        __syncthreads();
        int ti = (t >> 4) << 2, tj = (t & 15) << 2;
        float acc[4][4];
        #pragma unroll
        for (int a = 0; a < 4; a++)
            #pragma unroll
            for (int b = 0; b < 4; b++) acc[a][b] = 0.f;
        for (int k = 0; k < 128; k++) {
            float av[4], bv[4];
            #pragma unroll
            for (int a = 0; a < 4; a++) av[a] = Ps[k][ti + a];
            #pragma unroll
            for (int b = 0; b < 4; b++) bv[b] = Ps[k][tj + b];
            #pragma unroll
            for (int a = 0; a < 4; a++)
                #pragma unroll
                for (int b = 0; b < 4; b++) acc[a][b] = fmaf(av[a], bv[b], acc[a][b]);
        }
        #pragma unroll
        for (int a = 0; a < 4; a++)
            #pragma unroll
            for (int b = 0; b < 4; b++)
                g_Gp[c][(ti + a) * 64 + tj + b] = acc[a][b];
    }
    // pack P: slot (kk,tq) holds physical k = 16kk+4tq+{0,1}/{2,3}
    {
        int id = blockIdx.x * 256 + t;
        int lane = id & 31, g = lane >> 2, tq = lane & 3;
        int kk = id >> 8, j = (id >> 5) & 7;
        int n = 8 * j + g, k0 = 16 * kk + 4 * tq;
        float p00 = probe[(k0) * 64 + n],     p01 = probe[(k0 + 1) * 64 + n];
        float p10 = probe[(k0 + 2) * 64 + n], p11 = probe[(k0 + 3) * 64 + n];
        uint32_t h0, l0, h1, l1;
        split2(p00, p01, h0, l0);
        split2(p10, p11, h1, l1);
        g_PP[id] = make_uint4(h0, h1, l0, l1);
    }
}

// ---------------- fused main kernel ----------------
#define SMEM_WORDS 16448
#define SMEM_BYTES (SMEM_WORDS * 4)

__global__ void __launch_bounds__(256, 2)
k_main(const float* __restrict__ hs, const float* __restrict__ probe,
       float* __restrict__ out) {
    extern __shared__ uint32_t smw[];
    uint4* Bs = (uint4*)smw;

    const int t = threadIdx.x;
    const int wg = t >> 5, lane = t & 31, g = lane >> 2, tq = lane & 3;
    const size_t g0 = (size_t)blockIdx.x * MT;
    const size_t rowA = g0 + 16 * wg + g, rowB = rowA + 8;
    const float* hA = hs + rowA * FD;
    const float* hB = hs + rowB * FD;

    uint32_t sbase = (uint32_t)__cvta_generic_to_shared(smw);

    // ======== block 0: Gauss-Jordan inverse in smem, write Minv + MP ========
    if (blockIdx.x == 0) {
        float* A = (float*)smw;                 // 64 x 132 floats = 33792 B
        int r = t >> 2, cs = t & 3;
        int col0 = cs * 32;
        #pragma unroll 8
        for (int i = 0; i < 32; i++) {
            int col = col0 + i;
            if (col < 64) {
                float s = 0.f;
                #pragma unroll
                for (int p = 0; p < 8; p++) s += g_Gp[p][r * 64 + col];
                A[r * 132 + col] = s;
            } else {
                A[r * 132 + col] = (col - 64 == r) ? 1.f : 0.f;
            }
        }
        __syncthreads();
        for (int k = 0; k < 64; k++) {
            float inv = 1.f / A[k * 132 + k];
            float f = A[r * 132 + k];
            if (r == k) {
                #pragma unroll 8
                for (int i = 0; i < 32; i++) A[k * 132 + col0 + i] *= inv;
            }
            __syncthreads();
            if (r != k) {
                #pragma unroll 8
                for (int i = 0; i < 32; i++)
                    A[r * 132 + col0 + i] = fmaf(-f, A[k * 132 + col0 + i], A[r * 132 + col0 + i]);
            }
            __syncthreads();
        }
        #pragma unroll
        for (int i = 0; i < 16; i++) {
            int id = t + 256 * i;
            int rr = id >> 6, jj = id & 63;
            g_Minv[id] = A[rr * 132 + 64 + jj];
        }
        #pragma unroll
        for (int i = 0; i < 4; i++) {
            int id = t + 256 * i;
            int ln = id & 31, gg = ln >> 2, tb = ln & 3;
            int j = id >> 7, kk = (id >> 5) & 3;
            int n = 8 * j + gg, k0 = 16 * kk + 2 * tb;
            float m00 = A[k0 * 132 + 64 + n],       m01 = A[(k0 + 1) * 132 + 64 + n];
            float m10 = A[(k0 + 8) * 132 + 64 + n], m11 = A[(k0 + 9) * 132 + 64 + n];
            uint32_t h0, l0, h1, l1;
            split2(m00, m01, h0, l0);
            split2(m10, m11, h1, l1);
            g_MP[id] = make_uint4(h0, h1, l0, l1);
        }
        __threadfence();
        __syncthreads();
        if (t == 0) atomicExch(&g_flag_inv, 1);
        __syncthreads();
    }

    // prologue: stage GEMM1 B chunk 0 -> buf0
    #pragma unroll
    for (int q = 0; q < 4; q++)
        cpa16(sbase + (t + 256 * q) * 16, g_PP + t + 256 * q);
    CP_COMMIT;

    float acc1[8][4];
    #pragma unroll
    for (int j = 0; j < 8; j++)
        #pragma unroll
        for (int q = 0; q < 4; q++) acc1[j][q] = 0.f;
    float sqA = 0.f, sqB = 0.f;

    float4 pa[4], pb[4];
    #pragma unroll
    for (int kk = 0; kk < 4; kk++) {
        int c0 = 16 * kk + 4 * tq;
        pa[kk] = *(const float4*)(hA + c0);
        pb[kk] = *(const float4*)(hB + c0);
    }

    // ======== GEMM1: acc1 = H * P, K = 1024 (3-term split) ========
    for (int ch = 0; ch < NCH; ch++) {
        CP_WAIT0;
        __syncthreads();
        const int buf = ch & 1;
        if (ch + 1 < NCH) {
            const uint4* src = g_PP + (ch + 1) * 1024;
            #pragma unroll
            for (int q = 0; q < 4; q++)
                cpa16(sbase + (((buf ^ 1) * 1024 + t + 256 * q) * 16), src + t + 256 * q);
            CP_COMMIT;
        }
        uint32_t ah[4][4], al[4][4];
        #pragma unroll
        for (int kk = 0; kk < 4; kk++) {
            float4 a4 = pa[kk], b4 = pb[kk];
            sqA = fmaf(a4.x, a4.x, fmaf(a4.y, a4.y, fmaf(a4.z, a4.z, fmaf(a4.w, a4.w, sqA))));
            sqB = fmaf(b4.x, b4.x, fmaf(b4.y, b4.y, fmaf(b4.z, b4.z, fmaf(b4.w, b4.w, sqB))));
            split2(a4.x, a4.y, ah[kk][0], al[kk][0]);
            split2(b4.x, b4.y, ah[kk][1], al[kk][1]);
            split2(a4.z, a4.w, ah[kk][2], al[kk][2]);
            split2(b4.z, b4.w, ah[kk][3], al[kk][3]);
        }
        if (ch + 1 < NCH) {
            const int cb = (ch + 1) * 64 + 4 * tq;
            #pragma unroll
            for (int kk = 0; kk < 4; kk++) {
                int c0 = cb + 16 * kk;
                pa[kk] = *(const float4*)(hA + c0);
                pb[kk] = *(const float4*)(hB + c0);
            }
        }
        #pragma unroll
        for (int kk = 0; kk < 4; kk++)
            #pragma unroll
            for (int j = 0; j < 8; j += 2) {
                uint4 b0 = Bs[buf * 1024 + (kk * 8 + j) * 32 + lane];
                uint4 b1 = Bs[buf * 1024 + (kk * 8 + j + 1) * 32 + lane];
                mma_bf16(acc1[j],     ah[kk][0], ah[kk][1], ah[kk][2], ah[kk][3], b0.x, b0.y);
                mma_bf16(acc1[j + 1], ah[kk][0], ah[kk][1], ah[kk][2], ah[kk][3], b1.x, b1.y);
                mma_bf16(acc1[j],     ah[kk][0], ah[kk][1], ah[kk][2], ah[kk][3], b0.z, b0.w);
                mma_bf16(acc1[j + 1], ah[kk][0], ah[kk][1], ah[kk][2], ah[kk][3], b1.z, b1.w);
                mma_bf16(acc1[j],     al[kk][0], al[kk][1], al[kk][2], al[kk][3], b0.x, b0.y);
                mma_bf16(acc1[j + 1], al[kk][0], al[kk][1], al[kk][2], al[kk][3], b1.x, b1.y);
            }
    }

    sqA += __shfl_xor_sync(~0u, sqA, 1); sqA += __shfl_xor_sync(~0u, sqA, 2);
    sqB += __shfl_xor_sync(~0u, sqB, 1); sqB += __shfl_xor_sync(~0u, sqB, 2);

    __syncthreads();

    // ======== blocks 1..32: compute + pack W = P * Minv (hidden behind others' GEMM1) ========
    if (blockIdx.x >= 1 && blockIdx.x <= 32) {
        if (t == 0) { while (atomicAdd(&g_flag_inv, 0) == 0) __nanosleep(64); }
        __syncthreads();
        const int bw = blockIdx.x - 1;
        #pragma unroll
        for (int s = 0; s < 2; s++) {
            int fid = t + 256 * s;
            int Tl = fid >> 7, rem = fid & 127;
            int kk = rem >> 5, ln = rem & 31, gg = ln >> 2, tb = ln & 3;
            int jo = Tl & 1, pi = Tl >> 1;
            int bpair = bw * 2 + pi;
            int f = 16 * bpair + 4 * (gg >> 1) + 2 * jo + (gg & 1);
            int r0 = 16 * kk + 2 * tb;
            const float* pr = probe + f * 64;
            float a00 = 0.f, a01 = 0.f, a10 = 0.f, a11 = 0.f;
            #pragma unroll 8
            for (int k = 0; k < 64; k++) {
                float pv = pr[k];
                float2 m0 = *(const float2*)(g_Minv + k * 64 + r0);
                float2 m1 = *(const float2*)(g_Minv + k * 64 + r0 + 8);
                a00 = fmaf(pv, m0.x, a00); a01 = fmaf(pv, m0.y, a01);
                a10 = fmaf(pv, m1.x, a10); a11 = fmaf(pv, m1.y, a11);
            }
            uint32_t h0, l0, h1, l1;
            split2(a00, a01, h0, l0);
            split2(a10, a11, h1, l1);
            g_WP[(bpair * 2 + jo) * 128 + kk * 32 + ln] = make_uint4(h0, h1, l0, l1);
        }
        __threadfence();
        __syncthreads();
        if (t == 0) atomicAdd(&g_flag_wp, 1);
    }

    // wait until all W tiles are published
    if (t == 0) { while (atomicAdd(&g_flag_wp, 0) < 32) __nanosleep(64); }
    __syncthreads();

    // prologue: stage GEMM2 W chunk 0 -> buf0 (2048 uint4)
    #pragma unroll
    for (int q = 0; q < 8; q++)
        cpa16(sbase + (t + 256 * q) * 16, g_WP + t + 256 * q);
    CP_COMMIT;

    // ---- repack acc1 (C frags) into GEMM2 A frags ----
    uint32_t a2h[4][4], a2l[4][4];
    #pragma unroll
    for (int kk = 0; kk < 4; kk++) {
        split2(acc1[2 * kk][0],     acc1[2 * kk][1],     a2h[kk][0], a2l[kk][0]);
        split2(acc1[2 * kk][2],     acc1[2 * kk][3],     a2h[kk][1], a2l[kk][1]);
        split2(acc1[2 * kk + 1][0], acc1[2 * kk + 1][1], a2h[kk][2], a2l[kk][2]);
        split2(acc1[2 * kk + 1][2], acc1[2 * kk + 1][3], a2h[kk][3], a2l[kk][3]);
    }

    // ---- d3 = b * Minv; dot = b . d3; scales ----
    float dA = 0.f, dB = 0.f;
    #pragma unroll
    for (int jh = 0; jh < 2; jh++) {
        float accd[4][4];
        #pragma unroll
        for (int j = 0; j < 4; j++)
            #pragma unroll
            for (int q = 0; q < 4; q++) accd[j][q] = 0.f;
        #pragma unroll
        for (int kk = 0; kk < 4; kk++)
            #pragma unroll
            for (int j = 0; j < 4; j += 2) {
                uint4 b0 = g_MP[((jh * 4 + j) * 4 + kk) * 32 + lane];
                uint4 b1 = g_MP[((jh * 4 + j + 1) * 4 + kk) * 32 + lane];
                mma_bf16(accd[j],     a2h[kk][0], a2h[kk][1], a2h[kk][2], a2h[kk][3], b0.x, b0.y);
                mma_bf16(accd[j + 1], a2h[kk][0], a2h[kk][1], a2h[kk][2], a2h[kk][3], b1.x, b1.y);
                mma_bf16(accd[j],     a2h[kk][0], a2h[kk][1], a2h[kk][2], a2h[kk][3], b0.z, b0.w);
                mma_bf16(accd[j + 1], a2h[kk][0], a2h[kk][1], a2h[kk][2], a2h[kk][3], b1.z, b1.w);
                mma_bf16(accd[j],     a2l[kk][0], a2l[kk][1], a2l[kk][2], a2l[kk][3], b0.x, b0.y);
                mma_bf16(accd[j + 1], a2l[kk][0], a2l[kk][1], a2l[kk][2], a2l[kk][3], b1.x, b1.y);
            }
        #pragma unroll
        for (int j = 0; j < 4; j++) {
            int jj = jh * 4 + j;
            dA = fmaf(acc1[jj][0], accd[j][0], dA); dA = fmaf(acc1[jj][1], accd[j][1], dA);
            dB = fmaf(acc1[jj][2], accd[j][2], dB); dB = fmaf(acc1[jj][3], accd[j][3], dB);
        }
    }
    dA += __shfl_xor_sync(~0u, dA, 1); dA += __shfl_xor_sync(~0u, dA, 2);
    dB += __shfl_xor_sync(~0u, dB, 1); dB += __shfl_xor_sync(~0u, dB, 2);
    const float scA = sqrtf(sqA / fmaxf(sqA - dA, sqA * 1e-12f));
    const float scB = sqrtf(sqB / fmaxf(sqB - dB, sqB * 1e-12f));

    // ======== GEMM2 + fused epilogue: out = (H - b*Wt) * scale ========
    float* pA = out + rowA * FD;
    float* pB = out + rowB * FD;
    const bool fA = ((rowA & 4095) == 0);
    const bool fB = ((rowB & 4095) == 0);

    for (int nc = 0; nc < 8; nc++) {
        CP_WAIT0;
        __syncthreads();
        const int buf = nc & 1;
        if (nc + 1 < 8) {
            const uint4* src = g_WP + (nc + 1) * 2048;
            #pragma unroll
            for (int q = 0; q < 8; q++)
                cpa16(sbase + (((buf ^ 1) * 2048 + t + 256 * q) * 16), src + t + 256 * q);
            CP_COMMIT;
        }
        #pragma unroll
        for (int half = 0; half < 2; half++) {
            float4 hv0[4], hv1[4];
            #pragma unroll
            for (int p = 0; p < 4; p++) {
                int col = nc * 128 + half * 64 + 16 * p + 4 * tq;
                hv0[p] = *(const float4*)(hA + col);
                hv1[p] = *(const float4*)(hB + col);
            }
            float acc2[8][4];
            #pragma unroll
            for (int jl = 0; jl < 8; jl++)
                #pragma unroll
                for (int q = 0; q < 4; q++) acc2[jl][q] = 0.f;
            #pragma unroll
            for (int kk = 0; kk < 4; kk++)
                #pragma unroll
                for (int jl = 0; jl < 8; jl += 2) {
                    uint4 b0 = Bs[buf * 2048 + ((half * 8 + jl) * 4 + kk) * 32 + lane];
                    uint4 b1 = Bs[buf * 2048 + ((half * 8 + jl + 1) * 4 + kk) * 32 + lane];
                    mma_bf16(acc2[jl],     a2h[kk][0], a2h[kk][1], a2h[kk][2], a2h[kk][3], b0.x, b0.y);
                    mma_bf16(acc2[jl + 1], a2h[kk][0], a2h[kk][1], a2h[kk][2], a2h[kk][3], b1.x, b1.y);
                    mma_bf16(acc2[jl],     a2h[kk][0], a2h[kk][1], a2h[kk][2], a2h[kk][3], b0.z, b0.w);
                    mma_bf16(acc2[jl + 1], a2h[kk][0], a2h[kk][1], a2h[kk][2], a2h[kk][3], b1.z, b1.w);
                    mma_bf16(acc2[jl],     a2l[kk][0], a2l[kk][1], a2l[kk][2], a2l[kk][3], b0.x, b0.y);
                    mma_bf16(acc2[jl + 1], a2l[kk][0], a2l[kk][1], a2l[kk][2], a2l[kk][3], b1.x, b1.y);
                }
            #pragma unroll
            for (int p = 0; p < 4; p++) {
                int col = nc * 128 + half * 64 + 16 * p + 4 * tq;
                float4 o0, o1;
                o0.x = (hv0[p].x - acc2[2 * p][0]) * scA;
                o0.y = (hv0[p].y - acc2[2 * p][1]) * scA;
                o0.z = (hv0[p].z - acc2[2 * p + 1][0]) * scA;
                o0.w = (hv0[p].w - acc2[2 * p + 1][1]) * scA;
                o1.x = (hv1[p].x - acc2[2 * p][2]) * scB;
                o1.y = (hv1[p].y - acc2[2 * p][3]) * scB;
                o1.z = (hv1[p].z - acc2[2 * p + 1][2]) * scB;
                o1.w = (hv1[p].w - acc2[2 * p + 1][3]) * scB;
                if (fA) o0 = hv0[p];
                if (fB) o1 = hv1[p];
                __stcs((float4*)(pA + col), o0);
                __stcs((float4*)(pB + col), o1);
            }
        }
    }
}

extern "C" void kernel_launch(void* const* d_in, const int* in_sizes, int n_in,
                              void* d_out, int out_size) {
    const float* hs = (const float*)d_in[0];
    const float* probe = (const float*)d_in[1];
    float* out = (float*)d_out;

    k_prep1<<<64, 256>>>(probe);

    cudaFuncSetAttribute(k_main, cudaFuncAttributeMaxDynamicSharedMemorySize, SMEM_BYTES);
    int rows = in_sizes[0] / FD;            // 32768
    k_main<<<rows / MT, 256, SMEM_BYTES>>>(hs, probe, out);
}